// round 3
// baseline (speedup 1.0000x reference)
#include <cuda_runtime.h>
#include <math.h>

// Problem constants
#define NPTS   1048576
#define DH     256        // mlp_x hidden
#define R      64         // Tucker rank (all three)
#define HQ     128
#define HC     128
#define CIN    64
#define CORE_ELEMS (R*R*R)   // 262144
#define NG     32            // quad point-groups per axis (32 pts each)

// ---------------- scratch (device globals) -------------
__device__ float g_up[2][NG][HQ];     // partial u sums per (axis, group)
__device__ float g_syp[2][NG];        // partial sum(y)
__device__ float g_h[HC];             // core hidden tanh
__device__ float g_v[R];              // Tucker-contracted vector (atomic acc)

// ---------------- tanh helpers -------------
__device__ __forceinline__ float tanh_acc(float x) {
    float e, r;
    asm("ex2.approx.f32 %0, %1;" : "=f"(e) : "f"(x * 2.8853900817779268f));
    asm("rcp.approx.f32 %0, %1;" : "=f"(r) : "f"(e + 1.0f));
    return fmaf(-2.0f, r, 1.0f);
}

// packed f32x2 fma
__device__ __forceinline__ unsigned long long fma2(unsigned long long a,
                                                   unsigned long long b,
                                                   unsigned long long c) {
    unsigned long long d;
    asm("fma.rn.f32x2 %0, %1, %2, %3;" : "=l"(d) : "l"(a), "l"(b), "l"(c));
    return d;
}
__device__ __forceinline__ unsigned long long packf2(float lo, float hi) {
    unsigned long long d;
    asm("mov.b64 %0, {%1, %2};" : "=l"(d) : "f"(lo), "f"(hi));
    return d;
}
// tanh of an f32x2 pair via one f16x2 MUFU op; result back as f32x2
__device__ __forceinline__ unsigned long long tanh2(unsigned long long z) {
    float zlo, zhi, tlo, thi;
    unsigned hp;
    asm("mov.b64 {%0, %1}, %2;" : "=f"(zlo), "=f"(zhi) : "l"(z));
    asm("cvt.rn.f16x2.f32 %0, %1, %2;" : "=r"(hp) : "f"(zhi), "f"(zlo)); // a->hi, b->lo
    asm("tanh.approx.f16x2 %0, %1;" : "=r"(hp) : "r"(hp));
    asm("{ .reg .b16 lo, hi;\n\t"
        "  mov.b32 {lo, hi}, %2;\n\t"
        "  cvt.f32.f16 %0, lo;\n\t"
        "  cvt.f32.f16 %1, hi; }\n" : "=f"(tlo), "=f"(thi) : "r"(hp));
    return packf2(tlo, thi);
}

// ---------------- K1: quad partial sums + core hidden + zero g_v -------------
// grid: 65 blocks x 256. blocks 0..63: (axis = b>>5, group = b&31, 32 pts); block 64: aux.
__global__ void __launch_bounds__(256) k1(
    const float* __restrict__ qx0, const float* __restrict__ qx1,
    const float* __restrict__ eqp,
    const float* __restrict__ Wq01, const float* __restrict__ bq01,
    const float* __restrict__ Wq11, const float* __restrict__ bq11,
    const float* __restrict__ ci,   const float* __restrict__ Wc1,
    const float* __restrict__ bc1)
{
    int b = blockIdx.x;
    int t = threadIdx.x;

    if (b == 64) {
        if (t < R) g_v[t] = 0.f;                 // reset atomic accumulator
        if (t < HC) {
            float z = bc1[t];
            #pragma unroll 8
            for (int i = 0; i < CIN; i++) z = fmaf(ci[i], Wc1[i * HC + t], z);
            g_h[t] = tanh_acc(z);
        }
        return;
    }

    int ax = b >> 5, g = b & 31;
    const float* qx = ax ? qx1 : qx0;
    const float* Wq = ax ? Wq11 : Wq01;
    const float* bq = ax ? bq11 : bq01;

    __shared__ float sx[32], sy[32], red[256];

    if (t < 32) {
        float x = qx[g * 32 + t];
        float y = sinf(3.14159265358979323846f * eqp[0] * x);
        sx[t] = x; sy[t] = y;
    }
    __syncthreads();

    int k = t & 127, sub = t >> 7;   // 2 subsets x 16 points
    float W = Wq[k], bb = bq[k];
    float acc = 0.f;
    int c0 = sub * 16;
    #pragma unroll
    for (int c = 0; c < 16; c++) {
        float z = fmaf(sx[c0 + c], W, bb);
        acc = fmaf(sy[c0 + c], tanh_acc(z), acc);
    }
    red[t] = acc;
    __syncthreads();

    if (t < 128) g_up[ax][g][t] = red[t] + red[t + 128];
    else if (t < 160) {              // warp 4: parallel sum of sy
        float s = sy[t - 128];
        #pragma unroll
        for (int o = 16; o; o >>= 1) s += __shfl_xor_sync(0xffffffffu, s, o);
        if (t == 128) g_syp[ax][g] = s;
    }
}

// ---------------- K2: fused w12 prologue + Wc2 streaming dots + weighted atomic v ----
// grid: (129, 8) x 256. h=128 row is bc2 (weight 1.0).
__global__ void __launch_bounds__(256) k2(
    const float* __restrict__ Wc2, const float* __restrict__ bc2,
    const float* __restrict__ Wq02, const float* __restrict__ bq02,
    const float* __restrict__ Wq12, const float* __restrict__ bq12)
{
    __shared__ float su[2][HQ];
    __shared__ float s12[128];
    __shared__ float ssy[2];
    __shared__ __align__(16) float sw[R * R];   // 16 KB: w12
    __shared__ float sred[8][8];

    int t = threadIdx.x;
    int h = blockIdx.x, ga = blockIdx.y;

    {   // reduce partial u over 32 groups
        int ax = t >> 7, k = t & 127;
        float s = 0.f;
        #pragma unroll 8
        for (int g = 0; g < NG; g++) s += g_up[ax][g][k];
        su[ax][k] = s;
    }
    if (t < 2) {
        float s = 0.f;
        #pragma unroll 8
        for (int g = 0; g < NG; g++) s += g_syp[t][g];
        ssy[t] = s;
    }
    __syncthreads();

    if (t < 128) {
        int ax = t >> 6, j = t & 63;
        const float* W2 = ax ? Wq12 : Wq02;   // (128,64) row-major
        const float* b2 = ax ? bq12 : bq02;
        float s = ssy[ax] * b2[j];
        #pragma unroll 8
        for (int k = 0; k < HQ; k++) s = fmaf(su[ax][k], W2[k * R + j], s);
        s12[t] = s;
    }
    __syncthreads();

    for (int i = t; i < R * R; i += 256)
        sw[i] = s12[i >> 6] * s12[64 + (i & 63)];
    __syncthreads();

    // stream 128KB of Wc2 row h, dot against w12
    const float* row = (h < HC) ? (Wc2 + (size_t)h * CORE_ELEMS) : bc2;
    const float4* sw4 = (const float4*)sw;

    float acc[8];
    #pragma unroll
    for (int aa = 0; aa < 8; aa++) {
        int a = ga * 8 + aa;
        const float4* p = (const float4*)(row + (size_t)a * (R * R));
        float s = 0.f;
        #pragma unroll
        for (int i = 0; i < 4; i++) {
            float4 c  = p[t + i * 256];
            float4 ww = sw4[t + i * 256];
            s = fmaf(c.x, ww.x, fmaf(c.y, ww.y, fmaf(c.z, ww.z, fmaf(c.w, ww.w, s))));
        }
        acc[aa] = s;
    }

    #pragma unroll
    for (int aa = 0; aa < 8; aa++) {
        float s = acc[aa];
        #pragma unroll
        for (int o = 16; o; o >>= 1) s += __shfl_xor_sync(0xffffffffu, s, o);
        if ((t & 31) == 0) sred[aa][t >> 5] = s;
    }
    __syncthreads();
    if (t < 8) {
        float wh = (h < HC) ? g_h[h] : 1.0f;
        float s = 0.f;
        #pragma unroll
        for (int w = 0; w < 8; w++) s += sred[t][w];
        atomicAdd(&g_v[ga * 8 + t], wh * s);
    }
}

// ---------------- K3: w2v preamble + f16x2-tanh main loop -------------
// out[i] = sum_h tanh(x0*W0[h] + x1*W1[h] + b[h]) * w2v[h] + c
#define PPT 10
#define NPR (PPT/2)
__global__ void __launch_bounds__(256) k3(
    const float2* __restrict__ inp,
    const float* __restrict__ Wx1, const float* __restrict__ bx1,
    const float* __restrict__ Wx2, const float* __restrict__ bx2,
    float* __restrict__ out, int n)
{
    // per-h packed weights: [2h] = {W0pair, W1pair}, [2h+1] = {bpair, w2vpair}
    __shared__ __align__(16) float swraw[DH * 8];   // 8 KB
    __shared__ __align__(16) float sv[R];
    int t = threadIdx.x;

    if (t < R) sv[t] = g_v[t];
    __syncthreads();

    // w2v[t] = Wx2[t,:] . v ; c = bx2 . v
    float w2v = 0.f, cc = 0.f;
    {
        const float4* wrow = (const float4*)(Wx2 + t * R);
        const float4* brow = (const float4*)bx2;
        const float4* v4   = (const float4*)sv;
        #pragma unroll
        for (int a = 0; a < R / 4; a++) {
            float4 w = wrow[a], b = brow[a], v = v4[a];
            w2v = fmaf(w.x, v.x, fmaf(w.y, v.y, fmaf(w.z, v.z, fmaf(w.w, v.w, w2v))));
            cc  = fmaf(b.x, v.x, fmaf(b.y, v.y, fmaf(b.z, v.z, fmaf(b.w, v.w, cc))));
        }
    }
    {
        float w0 = Wx1[t], w1 = Wx1[DH + t], bb = bx1[t];
        ((float4*)swraw)[t * 2 + 0] = make_float4(w0, w0, w1, w1);
        ((float4*)swraw)[t * 2 + 1] = make_float4(bb, bb, w2v, w2v);
    }
    __syncthreads();

    const ulonglong2* swp = (const ulonglong2*)swraw;

    int base = blockIdx.x * (256 * PPT) + t;

    unsigned long long X0[NPR], X1[NPR], accp[NPR];
    #pragma unroll
    for (int pr = 0; pr < NPR; pr++) {
        int i0 = base + (2 * pr) * 256;
        int i1 = base + (2 * pr + 1) * 256;
        float2 a = (i0 < n) ? inp[i0] : make_float2(0.f, 0.f);
        float2 b = (i1 < n) ? inp[i1] : make_float2(0.f, 0.f);
        X0[pr] = packf2(a.x, b.x);
        X1[pr] = packf2(a.y, b.y);
        accp[pr] = packf2(0.f, 0.f);
    }

    #pragma unroll 4
    for (int h = 0; h < DH; h++) {
        ulonglong2 wa = swp[h * 2];        // {W0pair, W1pair}
        ulonglong2 wb = swp[h * 2 + 1];    // {bpair, w2vpair}
        #pragma unroll
        for (int pr = 0; pr < NPR; pr++) {
            unsigned long long z = fma2(X0[pr], wa.x, fma2(X1[pr], wa.y, wb.x));
            accp[pr] = fma2(tanh2(z), wb.y, accp[pr]);
        }
    }

    #pragma unroll
    for (int pr = 0; pr < NPR; pr++) {
        float alo, ahi;
        asm("mov.b64 {%0, %1}, %2;" : "=f"(alo), "=f"(ahi) : "l"(accp[pr]));
        int i0 = base + (2 * pr) * 256;
        int i1 = base + (2 * pr + 1) * 256;
        if (i0 < n) out[i0] = alo + cc;
        if (i1 < n) out[i1] = ahi + cc;
    }
}

// ---------------- launch -------------
extern "C" void kernel_launch(void* const* d_in, const int* in_sizes, int n_in,
                              void* d_out, int out_size)
{
    const float* input  = (const float*)d_in[0];
    const float* eqp    = (const float*)d_in[1];
    const float* qx0    = (const float*)d_in[2];
    const float* qx1    = (const float*)d_in[3];
    const float* ci     = (const float*)d_in[4];
    const float* Wx1    = (const float*)d_in[5];
    const float* bx1    = (const float*)d_in[6];
    const float* Wx2    = (const float*)d_in[7];
    const float* bx2    = (const float*)d_in[8];
    const float* Wq01   = (const float*)d_in[9];
    const float* bq01   = (const float*)d_in[10];
    const float* Wq02   = (const float*)d_in[11];
    const float* bq02   = (const float*)d_in[12];
    const float* Wq11   = (const float*)d_in[13];
    const float* bq11   = (const float*)d_in[14];
    const float* Wq12   = (const float*)d_in[15];
    const float* bq12   = (const float*)d_in[16];
    const float* Wc1    = (const float*)d_in[17];
    const float* bc1    = (const float*)d_in[18];
    const float* Wc2    = (const float*)d_in[19];
    const float* bc2    = (const float*)d_in[20];

    int n = in_sizes[0] / 2;

    k1 <<<65, 256>>>(qx0, qx1, eqp, Wq01, bq01, Wq11, bq11, ci, Wc1, bc1);
    k2 <<<dim3(129, 8), 256>>>(Wc2, bc2, Wq02, bq02, Wq12, bq12);

    int blocks = (n + 256 * PPT - 1) / (256 * PPT);   // 410 for n=1M
    // round up to a full 3-blocks/SM wave (148*3=444) for even load
    if (blocks < 444) blocks = 444;
    k3 <<<blocks, 256>>>((const float2*)input, Wx1, bx1, Wx2, bx2, (float*)d_out, n);
}

// round 4
// speedup vs baseline: 1.0168x; 1.0168x over previous
#include <cuda_runtime.h>
#include <math.h>

// Problem constants
#define NPTS   1048576
#define DH     256        // mlp_x hidden
#define R      64         // Tucker rank (all three)
#define HQ     128
#define HC     128
#define CIN    64
#define CORE_ELEMS (R*R*R)   // 262144
#define NG     32            // quad point-groups per axis (32 pts each)

// ---------------- scratch (device globals) -------------
__device__ float g_up[2][NG][HQ];     // partial u sums per (axis, group)
__device__ float g_syp[2][NG];        // partial sum(y)
__device__ float g_h[HC];             // core hidden tanh
__device__ float g_v[R];              // Tucker-contracted vector (atomic acc)

// ---------------- math helpers -------------
__device__ __forceinline__ float tanh_acc(float x) {
    float e, r;
    asm("ex2.approx.f32 %0, %1;" : "=f"(e) : "f"(x * 2.8853900817779268f));
    asm("rcp.approx.f32 %0, %1;" : "=f"(r) : "f"(e + 1.0f));
    return fmaf(-2.0f, r, 1.0f);
}
__device__ __forceinline__ unsigned long long fma2(unsigned long long a,
                                                   unsigned long long b,
                                                   unsigned long long c) {
    unsigned long long d;
    asm("fma.rn.f32x2 %0, %1, %2, %3;" : "=l"(d) : "l"(a), "l"(b), "l"(c));
    return d;
}
__device__ __forceinline__ unsigned long long packf2(float lo, float hi) {
    unsigned long long d;
    asm("mov.b64 %0, {%1, %2};" : "=l"(d) : "f"(lo), "f"(hi));
    return d;
}
// f32x2 z -> f16x2 tanh(z). Result halves: {lo = tanh(z.lo), hi = tanh(z.hi)}
__device__ __forceinline__ unsigned tanh2h(unsigned long long z) {
    float zl, zh; unsigned hp;
    asm("mov.b64 {%0, %1}, %2;" : "=f"(zl), "=f"(zh) : "l"(z));
    asm("cvt.rn.f16x2.f32 %0, %1, %2;" : "=r"(hp) : "f"(zh), "f"(zl)); // {hi=zh, lo=zl}
    asm("tanh.approx.f16x2 %0, %1;" : "=r"(hp) : "r"(hp));
    return hp;
}
__device__ __forceinline__ unsigned hfma2(unsigned a, unsigned b, unsigned c) {
    unsigned d;
    asm("fma.rn.f16x2 %0, %1, %2, %3;" : "=r"(d) : "r"(a), "r"(b), "r"(c));
    return d;
}
// f16x2 -> two f32
__device__ __forceinline__ void unpackh2(unsigned p, float& lo, float& hi) {
    asm("{ .reg .b16 l, h;\n\t"
        "  mov.b32 {l, h}, %2;\n\t"
        "  cvt.f32.f16 %0, l;\n\t"
        "  cvt.f32.f16 %1, h; }\n" : "=f"(lo), "=f"(hi) : "r"(p));
}
// broadcast f32 -> f16x2 {h,h}
__device__ __forceinline__ unsigned bcast_h2(float x) {
    unsigned d;
    asm("{ .reg .b16 h;\n\t"
        "  cvt.rn.f16.f32 h, %1;\n\t"
        "  mov.b32 %0, {h, h}; }\n" : "=r"(d) : "f"(x));
    return d;
}

// ---------------- K1: quad partial sums + core hidden + zero g_v -------------
__global__ void __launch_bounds__(256) k1(
    const float* __restrict__ qx0, const float* __restrict__ qx1,
    const float* __restrict__ eqp,
    const float* __restrict__ Wq01, const float* __restrict__ bq01,
    const float* __restrict__ Wq11, const float* __restrict__ bq11,
    const float* __restrict__ ci,   const float* __restrict__ Wc1,
    const float* __restrict__ bc1)
{
    int b = blockIdx.x;
    int t = threadIdx.x;

    if (b == 64) {
        if (t < R) g_v[t] = 0.f;
        if (t < HC) {
            float z = bc1[t];
            #pragma unroll 8
            for (int i = 0; i < CIN; i++) z = fmaf(ci[i], Wc1[i * HC + t], z);
            g_h[t] = tanh_acc(z);
        }
        return;
    }

    int ax = b >> 5, g = b & 31;
    const float* qx = ax ? qx1 : qx0;
    const float* Wq = ax ? Wq11 : Wq01;
    const float* bq = ax ? bq11 : bq01;

    __shared__ float sx[32], sy[32], red[256];

    if (t < 32) {
        float x = qx[g * 32 + t];
        float y = sinf(3.14159265358979323846f * eqp[0] * x);
        sx[t] = x; sy[t] = y;
    }
    __syncthreads();

    int k = t & 127, sub = t >> 7;
    float W = Wq[k], bb = bq[k];
    float acc = 0.f;
    int c0 = sub * 16;
    #pragma unroll
    for (int c = 0; c < 16; c++) {
        float z = fmaf(sx[c0 + c], W, bb);
        acc = fmaf(sy[c0 + c], tanh_acc(z), acc);
    }
    red[t] = acc;
    __syncthreads();

    if (t < 128) g_up[ax][g][t] = red[t] + red[t + 128];
    else if (t < 160) {
        float s = sy[t - 128];
        #pragma unroll
        for (int o = 16; o; o >>= 1) s += __shfl_xor_sync(0xffffffffu, s, o);
        if (t == 128) g_syp[ax][g] = s;
    }
}

// ---------------- K2: fused w12 prologue + Wc2 streaming dots + weighted atomic v ----
__global__ void __launch_bounds__(256) k2(
    const float* __restrict__ Wc2, const float* __restrict__ bc2,
    const float* __restrict__ Wq02, const float* __restrict__ bq02,
    const float* __restrict__ Wq12, const float* __restrict__ bq12)
{
    __shared__ float su[2][HQ];
    __shared__ float s12[128];
    __shared__ float ssy[2];
    __shared__ __align__(16) float sw[R * R];   // 16 KB: w12
    __shared__ float sred[8][8];

    int t = threadIdx.x;
    int h = blockIdx.x, ga = blockIdx.y;

    {
        int ax = t >> 7, k = t & 127;
        float s = 0.f;
        #pragma unroll 8
        for (int g = 0; g < NG; g++) s += g_up[ax][g][k];
        su[ax][k] = s;
    }
    if (t < 2) {
        float s = 0.f;
        #pragma unroll 8
        for (int g = 0; g < NG; g++) s += g_syp[t][g];
        ssy[t] = s;
    }
    __syncthreads();

    if (t < 128) {
        int ax = t >> 6, j = t & 63;
        const float* W2 = ax ? Wq12 : Wq02;
        const float* b2 = ax ? bq12 : bq02;
        float s = ssy[ax] * b2[j];
        #pragma unroll 8
        for (int k = 0; k < HQ; k++) s = fmaf(su[ax][k], W2[k * R + j], s);
        s12[t] = s;
    }
    __syncthreads();

    for (int i = t; i < R * R; i += 256)
        sw[i] = s12[i >> 6] * s12[64 + (i & 63)];
    __syncthreads();

    const float* row = (h < HC) ? (Wc2 + (size_t)h * CORE_ELEMS) : bc2;
    const float4* sw4 = (const float4*)sw;

    float acc[8];
    #pragma unroll
    for (int aa = 0; aa < 8; aa++) {
        int a = ga * 8 + aa;
        const float4* p = (const float4*)(row + (size_t)a * (R * R));
        float s = 0.f;
        #pragma unroll
        for (int i = 0; i < 4; i++) {
            float4 c  = p[t + i * 256];
            float4 ww = sw4[t + i * 256];
            s = fmaf(c.x, ww.x, fmaf(c.y, ww.y, fmaf(c.z, ww.z, fmaf(c.w, ww.w, s))));
        }
        acc[aa] = s;
    }

    #pragma unroll
    for (int aa = 0; aa < 8; aa++) {
        float s = acc[aa];
        #pragma unroll
        for (int o = 16; o; o >>= 1) s += __shfl_xor_sync(0xffffffffu, s, o);
        if ((t & 31) == 0) sred[aa][t >> 5] = s;
    }
    __syncthreads();
    if (t < 8) {
        float wh = (h < HC) ? g_h[h] : 1.0f;
        float s = 0.f;
        #pragma unroll
        for (int w = 0; w < 8; w++) s += sred[t][w];
        atomicAdd(&g_v[ga * 8 + t], wh * s);
    }
}

// ---------------- K3: w2v preamble (+range scaling) + f16x2 MAC main loop -------------
#define PPT 10
#define NPR (PPT/2)
__global__ void __launch_bounds__(256) k3(
    const float2* __restrict__ inp,
    const float* __restrict__ Wx1, const float* __restrict__ bx1,
    const float* __restrict__ Wx2, const float* __restrict__ bx2,
    float* __restrict__ out, int n)
{
    __shared__ __align__(16) ulonglong2 swA[DH];        // {w0pair, w1pair} f32x2
    __shared__ __align__(16) unsigned long long swB[DH]; // bpair f32x2
    __shared__ unsigned swC[DH];                         // w2v*scale as f16x2 {w,w}
    __shared__ __align__(16) float sv[R];
    __shared__ float smax[8];
    int t = threadIdx.x;

    if (t < R) sv[t] = g_v[t];
    __syncthreads();

    // w2v[t] = Wx2[t,:] . v ; c = bx2 . v
    float w2v = 0.f, cc = 0.f;
    {
        const float4* wrow = (const float4*)(Wx2 + t * R);
        const float4* brow = (const float4*)bx2;
        const float4* v4   = (const float4*)sv;
        #pragma unroll
        for (int a = 0; a < R / 4; a++) {
            float4 w = wrow[a], b = brow[a], v = v4[a];
            w2v = fmaf(w.x, v.x, fmaf(w.y, v.y, fmaf(w.z, v.z, fmaf(w.w, v.w, w2v))));
            cc  = fmaf(b.x, v.x, fmaf(b.y, v.y, fmaf(b.z, v.z, fmaf(b.w, v.w, cc))));
        }
    }

    // block max|w2v| -> exact power-of-2 scaling into f16-safe range
    {
        float m = fabsf(w2v);
        #pragma unroll
        for (int o = 16; o; o >>= 1) m = fmaxf(m, __shfl_xor_sync(0xffffffffu, m, o));
        if ((t & 31) == 0) smax[t >> 5] = m;
    }
    __syncthreads();
    float mx = smax[0];
    #pragma unroll
    for (int w = 1; w < 8; w++) mx = fmaxf(mx, smax[w]);

    float scale = 1.f, inv = 1.f;
    if (mx > 0.f) {
        int e; frexpf(mx, &e);               // mx in [0.5,1)*2^e
        scale = exp2f((float)(2 - e));       // scaled max in [2,4)
        inv   = exp2f((float)(e - 2));
    }

    {
        float w0 = Wx1[t], w1 = Wx1[DH + t], bb = bx1[t];
        swA[t] = make_ulonglong2(packf2(w0, w0), packf2(w1, w1));
        swB[t] = packf2(bb, bb);
        swC[t] = bcast_h2(w2v * scale);
    }
    __syncthreads();

    int base = blockIdx.x * (256 * PPT) + t;

    unsigned long long X0[NPR], X1[NPR];
    float aLo[NPR], aHi[NPR];
    #pragma unroll
    for (int pr = 0; pr < NPR; pr++) {
        int i0 = base + (2 * pr) * 256;
        int i1 = base + (2 * pr + 1) * 256;
        float2 a = (i0 < n) ? inp[i0] : make_float2(0.f, 0.f);
        float2 b = (i1 < n) ? inp[i1] : make_float2(0.f, 0.f);
        X0[pr] = packf2(a.x, b.x);
        X1[pr] = packf2(a.y, b.y);
        aLo[pr] = 0.f; aHi[pr] = 0.f;
    }

    for (int hb = 0; hb < DH; hb += 8) {
        unsigned a16[NPR];
        #pragma unroll
        for (int pr = 0; pr < NPR; pr++) a16[pr] = 0u;

        #pragma unroll
        for (int hh = 0; hh < 8; hh++) {
            int h = hb + hh;
            ulonglong2 wz = swA[h];
            unsigned long long bp = swB[h];
            unsigned wv = swC[h];
            #pragma unroll
            for (int pr = 0; pr < NPR; pr++) {
                unsigned long long z = fma2(X0[pr], wz.x, fma2(X1[pr], wz.y, bp));
                a16[pr] = hfma2(tanh2h(z), wv, a16[pr]);
            }
        }
        #pragma unroll
        for (int pr = 0; pr < NPR; pr++) {
            float lo, hi;
            unpackh2(a16[pr], lo, hi);
            aLo[pr] += lo; aHi[pr] += hi;
        }
    }

    #pragma unroll
    for (int pr = 0; pr < NPR; pr++) {
        int i0 = base + (2 * pr) * 256;
        int i1 = base + (2 * pr + 1) * 256;
        if (i0 < n) out[i0] = fmaf(aLo[pr], inv, cc);
        if (i1 < n) out[i1] = fmaf(aHi[pr], inv, cc);
    }
}

// ---------------- launch -------------
extern "C" void kernel_launch(void* const* d_in, const int* in_sizes, int n_in,
                              void* d_out, int out_size)
{
    const float* input  = (const float*)d_in[0];
    const float* eqp    = (const float*)d_in[1];
    const float* qx0    = (const float*)d_in[2];
    const float* qx1    = (const float*)d_in[3];
    const float* ci     = (const float*)d_in[4];
    const float* Wx1    = (const float*)d_in[5];
    const float* bx1    = (const float*)d_in[6];
    const float* Wx2    = (const float*)d_in[7];
    const float* bx2    = (const float*)d_in[8];
    const float* Wq01   = (const float*)d_in[9];
    const float* bq01   = (const float*)d_in[10];
    const float* Wq02   = (const float*)d_in[11];
    const float* bq02   = (const float*)d_in[12];
    const float* Wq11   = (const float*)d_in[13];
    const float* bq11   = (const float*)d_in[14];
    const float* Wq12   = (const float*)d_in[15];
    const float* bq12   = (const float*)d_in[16];
    const float* Wc1    = (const float*)d_in[17];
    const float* bc1    = (const float*)d_in[18];
    const float* Wc2    = (const float*)d_in[19];
    const float* bc2    = (const float*)d_in[20];

    int n = in_sizes[0] / 2;

    k1 <<<65, 256>>>(qx0, qx1, eqp, Wq01, bq01, Wq11, bq11, ci, Wc1, bc1);
    k2 <<<dim3(129, 8), 256>>>(Wc2, bc2, Wq02, bq02, Wq12, bq12);

    int blocks = (n + 256 * PPT - 1) / (256 * PPT);
    if (blocks < 444) blocks = 444;   // full 3-blocks/SM wave
    k3 <<<blocks, 256>>>((const float2*)input, Wx1, bx1, Wx2, bx2, (float*)d_out, n);
}